// round 7
// baseline (speedup 1.0000x reference)
#include <cuda_runtime.h>
#include <cuda_bf16.h>
#include <cstdint>

#define NTOK 8192
#define KDIM 512
#define DDIM 4096

#define BM 128
#define BN 256
#define BK 32
#define STAGES 4
#define KITERS (KDIM / BK)   // 16
#define DTILES (DDIM / BN)   // 16
#define NTILES (NTOK / BM)   // 64
#define PSLOTS (DTILES * 4)  // 64

#define STAGE_BYTES 49152
#define OFF_AH 0
#define OFF_AL 8192
#define OFF_BH 16384
#define OFF_BL 32768
#define SMEM_TOTAL (STAGES * STAGE_BYTES)  // 196608 B

__device__ __align__(16) __nv_bfloat16 g_Fhi[NTOK * KDIM];
__device__ __align__(16) __nv_bfloat16 g_Flo[NTOK * KDIM];
__device__ __align__(16) __nv_bfloat16 g_Ethi[DDIM * KDIM];  // E^T: [d][k], k contiguous
__device__ __align__(16) __nv_bfloat16 g_Etlo[DDIM * KDIM];
__device__ float g_partial[(size_t)PSLOTS * NTOK];

__device__ __forceinline__ unsigned smem_u32(const void* p) {
    unsigned a;
    asm("{ .reg .u64 t; cvta.to.shared.u64 t, %1; cvt.u32.u64 %0, t; }" : "=r"(a) : "l"(p));
    return a;
}

#define CP16(s, g) \
    asm volatile("cp.async.cg.shared.global [%0], [%1], 16;" :: "r"(s), "l"(g) : "memory")
#define CP_COMMIT() asm volatile("cp.async.commit_group;" ::: "memory")

#define LDSM4(R, addr)                                                        \
    asm volatile("ldmatrix.sync.aligned.m8n8.x4.shared.b16 {%0,%1,%2,%3}, [%4];" \
        : "=r"((R)[0]), "=r"((R)[1]), "=r"((R)[2]), "=r"((R)[3]) : "r"(addr))

#define MMA(C, A, b0, b1)                                                     \
    asm volatile("mma.sync.aligned.m16n8k16.row.col.f32.bf16.bf16.f32 "       \
        "{%0,%1,%2,%3}, {%4,%5,%6,%7}, {%8,%9}, {%0,%1,%2,%3};"               \
        : "+f"((C)[0]), "+f"((C)[1]), "+f"((C)[2]), "+f"((C)[3])              \
        : "r"((A)[0]), "r"((A)[1]), "r"((A)[2]), "r"((A)[3]), "r"(b0), "r"(b1))

// ---------------- prep: bf16 hi/lo splits ----------------
__global__ void split_f_kernel(const float* __restrict__ f) {
    int i = blockIdx.x * blockDim.x + threadIdx.x;
    if (i < NTOK * KDIM) {
        float x = f[i];
        __nv_bfloat16 h = __float2bfloat16(x);
        g_Fhi[i] = h;
        g_Flo[i] = __float2bfloat16(x - __bfloat162float(h));
    }
}

__global__ void split_e_t_kernel(const float* __restrict__ e) {  // e: [KDIM][DDIM]
    __shared__ float t[32][33];
    int d0 = blockIdx.x * 32, k0 = blockIdx.y * 32;
    int tx = threadIdx.x, ty = threadIdx.y;
#pragma unroll
    for (int i = ty; i < 32; i += 8)
        t[i][tx] = e[(size_t)(k0 + i) * DDIM + d0 + tx];
    __syncthreads();
#pragma unroll
    for (int i = ty; i < 32; i += 8) {
        float x = t[tx][i];  // E[k0+tx][d0+i]
        size_t o = (size_t)(d0 + i) * KDIM + k0 + tx;
        __nv_bfloat16 h = __float2bfloat16(x);
        g_Ethi[o] = h;
        g_Etlo[o] = __float2bfloat16(x - __bfloat162float(h));
    }
}

__global__ void reduce_kernel(float* __restrict__ out) {
    int n = blockIdx.x * blockDim.x + threadIdx.x;
    if (n < NTOK) {
        float s = 0.f;
#pragma unroll
        for (int i = 0; i < PSLOTS; i++) s += g_partial[(size_t)i * NTOK + n];
        out[n] = s;
    }
}

// ---------------- main: bf16x3 GEMM + fused diagonal ----------------
__global__ void __launch_bounds__(256, 1)
mm_diag_kernel(const float* __restrict__ wmat, const float* __restrict__ bvec) {
    extern __shared__ char smem[];
    const unsigned sb = smem_u32(smem);
    const int tid  = threadIdx.x;
    const int lane = tid & 31;
    const int wid  = tid >> 5;
    const int wm   = wid & 1;   // 2 warps over tokens (64 each)
    const int wn   = wid >> 1;  // 4 warps over d (64 each)
    const int dg0  = blockIdx.x * BN;
    const int n0   = blockIdx.y * BM;

    const char* gAh = (const char*)g_Fhi;
    const char* gAl = (const char*)g_Flo;
    const char* gBh = (const char*)g_Ethi;
    const char* gBl = (const char*)g_Etlo;

    auto load_stage = [&](int kc, int s) {
        unsigned base = sb + (unsigned)s * STAGE_BYTES;
#pragma unroll
        for (int t = tid; t < 512; t += 256) {  // A: 128 rows x 4 chunks(16B)
            int row = t >> 2, cs = t & 3;
            unsigned soff = (unsigned)(row * 64) + (unsigned)((cs ^ ((row >> 1) & 3)) << 4);
            size_t goff = ((size_t)(n0 + row) * KDIM + (size_t)kc * BK + cs * 8) * 2;
            CP16(base + OFF_AH + soff, gAh + goff);
            CP16(base + OFF_AL + soff, gAl + goff);
        }
#pragma unroll
        for (int t = tid; t < 1024; t += 256) {  // B: 256 rows x 4 chunks
            int row = t >> 2, cs = t & 3;
            unsigned soff = (unsigned)(row * 64) + (unsigned)((cs ^ ((row >> 1) & 3)) << 4);
            size_t goff = ((size_t)(dg0 + row) * KDIM + (size_t)kc * BK + cs * 8) * 2;
            CP16(base + OFF_BH + soff, gBh + goff);
            CP16(base + OFF_BL + soff, gBl + goff);
        }
    };

    // prologue: stages 0..STAGES-2
    for (int s = 0; s < STAGES - 1; s++) { load_stage(s, s); CP_COMMIT(); }

    // precompute per-lane ldmatrix tile offsets (kk=0); kk=1 -> XOR 32
    unsigned offA[4], offB[4];
#pragma unroll
    for (int ma = 0; ma < 4; ma++) {
        int row = wm * 64 + ma * 16 + (lane & 15);
        int ch  = lane >> 4;
        offA[ma] = (unsigned)(row * 64) + (unsigned)((ch ^ ((row >> 1) & 3)) << 4);
    }
#pragma unroll
    for (int nb = 0; nb < 4; nb++) {
        int row = wn * 64 + nb * 16 + (lane & 15);
        int ch  = lane >> 4;
        offB[nb] = (unsigned)(row * 64) + (unsigned)((ch ^ ((row >> 1) & 3)) << 4);
    }

    float c[4][8][4];
#pragma unroll
    for (int i = 0; i < 4; i++)
#pragma unroll
        for (int j = 0; j < 8; j++)
#pragma unroll
            for (int r = 0; r < 4; r++) c[i][j][r] = 0.f;

    for (int it = 0; it < KITERS; it++) {
        asm volatile("cp.async.wait_group %0;" :: "n"(STAGES - 2));
        __syncthreads();
        int ns = it + STAGES - 1;
        if (ns < KITERS) load_stage(ns, ns & (STAGES - 1));
        CP_COMMIT();

        unsigned base = sb + (unsigned)(it & (STAGES - 1)) * STAGE_BYTES;
#pragma unroll
        for (int kk = 0; kk < 2; kk++) {
            unsigned kx = (unsigned)(kk << 5);
            uint32_t Ah[4][4], Bh[4][4];
#pragma unroll
            for (int ma = 0; ma < 4; ma++) LDSM4(Ah[ma], base + OFF_AH + (offA[ma] ^ kx));
#pragma unroll
            for (int nb = 0; nb < 4; nb++) LDSM4(Bh[nb], base + OFF_BH + (offB[nb] ^ kx));
            // hh
#pragma unroll
            for (int ma = 0; ma < 4; ma++)
#pragma unroll
                for (int nb = 0; nb < 4; nb++) {
                    MMA(c[ma][2 * nb],     Ah[ma], Bh[nb][0], Bh[nb][2]);
                    MMA(c[ma][2 * nb + 1], Ah[ma], Bh[nb][1], Bh[nb][3]);
                }
            // lh: Al * Bh
            {
                uint32_t Al[4][4];
#pragma unroll
                for (int ma = 0; ma < 4; ma++) LDSM4(Al[ma], base + OFF_AL + (offA[ma] ^ kx));
#pragma unroll
                for (int ma = 0; ma < 4; ma++)
#pragma unroll
                    for (int nb = 0; nb < 4; nb++) {
                        MMA(c[ma][2 * nb],     Al[ma], Bh[nb][0], Bh[nb][2]);
                        MMA(c[ma][2 * nb + 1], Al[ma], Bh[nb][1], Bh[nb][3]);
                    }
            }
            // hl: Ah * Bl
            {
                uint32_t Bl[4][4];
#pragma unroll
                for (int nb = 0; nb < 4; nb++) LDSM4(Bl[nb], base + OFF_BL + (offB[nb] ^ kx));
#pragma unroll
                for (int ma = 0; ma < 4; ma++)
#pragma unroll
                    for (int nb = 0; nb < 4; nb++) {
                        MMA(c[ma][2 * nb],     Ah[ma], Bl[nb][0], Bl[nb][2]);
                        MMA(c[ma][2 * nb + 1], Ah[ma], Bl[nb][1], Bl[nb][3]);
                    }
            }
        }
    }

    // ---- fused epilogue: partial[n] += sum_d (y + b[d]) * w[d][n] ----
    const int g  = lane >> 2;  // row within 8
    const int cc = lane & 3;   // col group
    float rowacc[8];
#pragma unroll
    for (int ma = 0; ma < 4; ma++) {
#pragma unroll
        for (int rh = 0; rh < 2; rh++) {
            int n = n0 + wm * 64 + ma * 16 + g + rh * 8;
            float acc = 0.f;
#pragma unroll
            for (int j = 0; j < 8; j++) {
#pragma unroll
                for (int cb = 0; cb < 2; cb++) {
                    int d = dg0 + wn * 64 + j * 8 + cc * 2 + cb;
                    float y = c[ma][j][rh * 2 + cb] + __ldg(&bvec[d]);
                    acc = fmaf(y, __ldg(&wmat[(size_t)d * NTOK + n]), acc);
                }
            }
            rowacc[ma * 2 + rh] = acc;
        }
    }
#pragma unroll
    for (int i = 0; i < 8; i++) {
        rowacc[i] += __shfl_xor_sync(0xFFFFFFFFu, rowacc[i], 1);
        rowacc[i] += __shfl_xor_sync(0xFFFFFFFFu, rowacc[i], 2);
    }
    if (cc == 0) {
        int slot = blockIdx.x * 4 + wn;
#pragma unroll
        for (int ma = 0; ma < 4; ma++)
#pragma unroll
            for (int rh = 0; rh < 2; rh++) {
                int n = n0 + wm * 64 + ma * 16 + g + rh * 8;
                g_partial[(size_t)slot * NTOK + n] = rowacc[ma * 2 + rh];
            }
    }
}

// ---------------- launch ----------------
extern "C" void kernel_launch(void* const* d_in, const int* in_sizes, int n_in,
                              void* d_out, int out_size) {
    const float* features = (const float*)d_in[0];  // [8192, 512]
    const float* w        = (const float*)d_in[1];  // [4096, 8192]
    const float* E        = (const float*)d_in[2];  // [512, 4096]
    const float* b        = (const float*)d_in[3];  // [4096]
    float* out            = (float*)d_out;          // [8192]

    cudaFuncSetAttribute(mm_diag_kernel, cudaFuncAttributeMaxDynamicSharedMemorySize, SMEM_TOTAL);

    split_f_kernel<<<(NTOK * KDIM + 255) / 256, 256>>>(features);
    split_e_t_kernel<<<dim3(DDIM / 32, KDIM / 32), dim3(32, 8)>>>(E);
    mm_diag_kernel<<<dim3(DTILES, NTILES), 256, SMEM_TOTAL>>>(w, b);
    reduce_kernel<<<(NTOK + 255) / 256, 256>>>(out);
}

// round 8
// speedup vs baseline: 1.0087x; 1.0087x over previous
#include <cuda_runtime.h>
#include <cuda_bf16.h>
#include <cstdint>

#define NTOK 8192
#define KDIM 512
#define DDIM 4096

#define BM 128
#define BN 256
#define BK 64
#define KITERS (KDIM / BK)   // 8
#define DTILES (DDIM / BN)   // 16
#define NTILES (NTOK / BM)   // 64
#define PSLOTS (DTILES * 8)  // 128

#define STAGE_BYTES 98304
#define OFF_AH 0
#define OFF_AL 16384
#define OFF_BH 32768
#define OFF_BL 65536
#define SMEM_TOTAL (2 * STAGE_BYTES)  // 196608 B

__device__ __align__(16) __nv_bfloat16 g_Fhi[NTOK * KDIM];
__device__ __align__(16) __nv_bfloat16 g_Flo[NTOK * KDIM];
__device__ __align__(16) __nv_bfloat16 g_Ethi[DDIM * KDIM];  // E^T: [d][k]
__device__ __align__(16) __nv_bfloat16 g_Etlo[DDIM * KDIM];
__device__ float g_partial[(size_t)PSLOTS * NTOK];

__device__ __forceinline__ unsigned smem_u32(const void* p) {
    unsigned a;
    asm("{ .reg .u64 t; cvta.to.shared.u64 t, %1; cvt.u32.u64 %0, t; }" : "=r"(a) : "l"(p));
    return a;
}

#define CP16(s, g) \
    asm volatile("cp.async.cg.shared.global [%0], [%1], 16;" :: "r"(s), "l"(g) : "memory")
#define CP_COMMIT() asm volatile("cp.async.commit_group;" ::: "memory")
#define CP_WAIT0()  asm volatile("cp.async.wait_group 0;" ::: "memory")

#define LDSM4(R, addr)                                                        \
    asm volatile("ldmatrix.sync.aligned.m8n8.x4.shared.b16 {%0,%1,%2,%3}, [%4];" \
        : "=r"((R)[0]), "=r"((R)[1]), "=r"((R)[2]), "=r"((R)[3]) : "r"(addr))

#define MMA(C, A, b0, b1)                                                     \
    asm volatile("mma.sync.aligned.m16n8k16.row.col.f32.bf16.bf16.f32 "       \
        "{%0,%1,%2,%3}, {%4,%5,%6,%7}, {%8,%9}, {%0,%1,%2,%3};"               \
        : "+f"((C)[0]), "+f"((C)[1]), "+f"((C)[2]), "+f"((C)[3])              \
        : "r"((A)[0]), "r"((A)[1]), "r"((A)[2]), "r"((A)[3]), "r"(b0), "r"(b1))

// ---------------- prep: bf16 hi/lo splits ----------------
__global__ void split_f_kernel(const float* __restrict__ f) {
    int i = blockIdx.x * blockDim.x + threadIdx.x;
    if (i < NTOK * KDIM) {
        float x = f[i];
        __nv_bfloat16 h = __float2bfloat16(x);
        g_Fhi[i] = h;
        g_Flo[i] = __float2bfloat16(x - __bfloat162float(h));
    }
}

__global__ void split_e_t_kernel(const float* __restrict__ e) {  // e: [KDIM][DDIM]
    __shared__ float t[32][33];
    int d0 = blockIdx.x * 32, k0 = blockIdx.y * 32;
    int tx = threadIdx.x, ty = threadIdx.y;
#pragma unroll
    for (int i = ty; i < 32; i += 8)
        t[i][tx] = e[(size_t)(k0 + i) * DDIM + d0 + tx];
    __syncthreads();
#pragma unroll
    for (int i = ty; i < 32; i += 8) {
        float x = t[tx][i];  // E[k0+tx][d0+i]
        size_t o = (size_t)(d0 + i) * KDIM + k0 + tx;
        __nv_bfloat16 h = __float2bfloat16(x);
        g_Ethi[o] = h;
        g_Etlo[o] = __float2bfloat16(x - __bfloat162float(h));
    }
}

__global__ void reduce_kernel(float* __restrict__ out) {
    int n = blockIdx.x * blockDim.x + threadIdx.x;
    if (n < NTOK) {
        float s = 0.f;
#pragma unroll
        for (int i = 0; i < PSLOTS; i++) s += g_partial[(size_t)i * NTOK + n];
        out[n] = s;
    }
}

// ---------------- main: bf16x3 GEMM + fused diagonal ----------------
// 512 threads: warp grid 2(m) x 8(n); warp tile 64x32. BK=64, 2-stage pipeline.
__global__ void __launch_bounds__(512, 1)
mm_diag_kernel(const float* __restrict__ wmat, const float* __restrict__ bvec) {
    extern __shared__ char smem[];
    const unsigned sb = smem_u32(smem);
    const int tid  = threadIdx.x;
    const int lane = tid & 31;
    const int wid  = tid >> 5;
    const int wm   = wid & 1;   // 2 warps over tokens (64 each)
    const int wn   = wid >> 1;  // 8 warps over d (32 each)
    const int dg0  = blockIdx.x * BN;
    const int n0   = blockIdx.y * BM;

    const char* gAh = (const char*)g_Fhi;
    const char* gAl = (const char*)g_Flo;
    const char* gBh = (const char*)g_Ethi;
    const char* gBl = (const char*)g_Etlo;

    // rows are 128B (64 bf16 = one BK chunk); swizzle: chunk ^= (row & 7)
    auto load_stage = [&](int kc, int s) {
        unsigned base = sb + (unsigned)s * STAGE_BYTES;
#pragma unroll
        for (int t = tid; t < 1024; t += 512) {  // A: 128 rows x 8 chunks(16B)
            int row = t >> 3, cs = t & 7;
            unsigned soff = (unsigned)(row * 128) + (unsigned)((cs ^ (row & 7)) << 4);
            size_t goff = ((size_t)(n0 + row) * KDIM + (size_t)kc * BK + cs * 8) * 2;
            CP16(base + OFF_AH + soff, gAh + goff);
            CP16(base + OFF_AL + soff, gAl + goff);
        }
#pragma unroll
        for (int t = tid; t < 2048; t += 512) {  // B: 256 rows x 8 chunks
            int row = t >> 3, cs = t & 7;
            unsigned soff = (unsigned)(row * 128) + (unsigned)((cs ^ (row & 7)) << 4);
            size_t goff = ((size_t)(dg0 + row) * KDIM + (size_t)kc * BK + cs * 8) * 2;
            CP16(base + OFF_BH + soff, gBh + goff);
            CP16(base + OFF_BL + soff, gBl + goff);
        }
    };

    load_stage(0, 0);
    CP_COMMIT();

    // per-lane ldmatrix base offsets (kk=0); kk step -> XOR (kk<<5)
    unsigned offA[4], offB[2];
#pragma unroll
    for (int ma = 0; ma < 4; ma++) {
        int row = wm * 64 + ma * 16 + (lane & 15);
        int ch  = lane >> 4;
        offA[ma] = (unsigned)(row * 128) + (unsigned)((ch ^ (row & 7)) << 4);
    }
#pragma unroll
    for (int nb = 0; nb < 2; nb++) {
        int row = wn * 32 + nb * 16 + (lane & 15);
        int ch  = lane >> 4;
        offB[nb] = (unsigned)(row * 128) + (unsigned)((ch ^ (row & 7)) << 4);
    }

    float c[4][4][4];
#pragma unroll
    for (int i = 0; i < 4; i++)
#pragma unroll
        for (int j = 0; j < 4; j++)
#pragma unroll
            for (int r = 0; r < 4; r++) c[i][j][r] = 0.f;

    for (int it = 0; it < KITERS; it++) {
        CP_WAIT0();          // stage `it` resident
        __syncthreads();     // all warps done with the other buffer; data visible
        if (it + 1 < KITERS) load_stage(it + 1, (it + 1) & 1);
        CP_COMMIT();

        unsigned base = sb + (unsigned)(it & 1) * STAGE_BYTES;
#pragma unroll
        for (int kk = 0; kk < 4; kk++) {
            unsigned kx = (unsigned)(kk << 5);
            uint32_t Ah[4][4], Bh[2][4];
#pragma unroll
            for (int ma = 0; ma < 4; ma++) LDSM4(Ah[ma], base + OFF_AH + (offA[ma] ^ kx));
#pragma unroll
            for (int nb = 0; nb < 2; nb++) LDSM4(Bh[nb], base + OFF_BH + (offB[nb] ^ kx));
            // hh
#pragma unroll
            for (int ma = 0; ma < 4; ma++)
#pragma unroll
                for (int nb = 0; nb < 2; nb++) {
                    MMA(c[ma][2 * nb],     Ah[ma], Bh[nb][0], Bh[nb][2]);
                    MMA(c[ma][2 * nb + 1], Ah[ma], Bh[nb][1], Bh[nb][3]);
                }
            // lh: Al * Bh  (Al dies after this block)
            {
                uint32_t Al[4][4];
#pragma unroll
                for (int ma = 0; ma < 4; ma++) LDSM4(Al[ma], base + OFF_AL + (offA[ma] ^ kx));
#pragma unroll
                for (int ma = 0; ma < 4; ma++)
#pragma unroll
                    for (int nb = 0; nb < 2; nb++) {
                        MMA(c[ma][2 * nb],     Al[ma], Bh[nb][0], Bh[nb][2]);
                        MMA(c[ma][2 * nb + 1], Al[ma], Bh[nb][1], Bh[nb][3]);
                    }
            }
            // hl: Ah * Bl
            {
                uint32_t Bl[2][4];
#pragma unroll
                for (int nb = 0; nb < 2; nb++) LDSM4(Bl[nb], base + OFF_BL + (offB[nb] ^ kx));
#pragma unroll
                for (int ma = 0; ma < 4; ma++)
#pragma unroll
                    for (int nb = 0; nb < 2; nb++) {
                        MMA(c[ma][2 * nb],     Ah[ma], Bl[nb][0], Bl[nb][2]);
                        MMA(c[ma][2 * nb + 1], Ah[ma], Bl[nb][1], Bl[nb][3]);
                    }
            }
        }
    }

    // ---- fused epilogue: partial[n] += sum_d (y + b[d]) * w[d][n] ----
    const int g  = lane >> 2;  // row within 8
    const int cc = lane & 3;   // col group
    float rowacc[8];
#pragma unroll
    for (int ma = 0; ma < 4; ma++) {
#pragma unroll
        for (int rh = 0; rh < 2; rh++) {
            int n = n0 + wm * 64 + ma * 16 + g + rh * 8;
            float acc = 0.f;
#pragma unroll
            for (int j = 0; j < 4; j++) {
#pragma unroll
                for (int cb = 0; cb < 2; cb++) {
                    int d = dg0 + wn * 32 + j * 8 + cc * 2 + cb;
                    float y = c[ma][j][rh * 2 + cb] + __ldg(&bvec[d]);
                    acc = fmaf(y, __ldg(&wmat[(size_t)d * NTOK + n]), acc);
                }
            }
            rowacc[ma * 2 + rh] = acc;
        }
    }
#pragma unroll
    for (int i = 0; i < 8; i++) {
        rowacc[i] += __shfl_xor_sync(0xFFFFFFFFu, rowacc[i], 1);
        rowacc[i] += __shfl_xor_sync(0xFFFFFFFFu, rowacc[i], 2);
    }
    if (cc == 0) {
        int slot = blockIdx.x * 8 + wn;
#pragma unroll
        for (int ma = 0; ma < 4; ma++)
#pragma unroll
            for (int rh = 0; rh < 2; rh++) {
                int n = n0 + wm * 64 + ma * 16 + g + rh * 8;
                g_partial[(size_t)slot * NTOK + n] = rowacc[ma * 2 + rh];
            }
    }
}

// ---------------- launch ----------------
extern "C" void kernel_launch(void* const* d_in, const int* in_sizes, int n_in,
                              void* d_out, int out_size) {
    const float* features = (const float*)d_in[0];  // [8192, 512]
    const float* w        = (const float*)d_in[1];  // [4096, 8192]
    const float* E        = (const float*)d_in[2];  // [512, 4096]
    const float* b        = (const float*)d_in[3];  // [4096]
    float* out            = (float*)d_out;          // [8192]

    cudaFuncSetAttribute(mm_diag_kernel, cudaFuncAttributeMaxDynamicSharedMemorySize, SMEM_TOTAL);

    split_f_kernel<<<(NTOK * KDIM + 255) / 256, 256>>>(features);
    split_e_t_kernel<<<dim3(DDIM / 32, KDIM / 32), dim3(32, 8)>>>(E);
    mm_diag_kernel<<<dim3(DTILES, NTILES), 512, SMEM_TOTAL>>>(w, b);
    reduce_kernel<<<(NTOK + 255) / 256, 256>>>(out);
}